// round 10
// baseline (speedup 1.0000x reference)
#include <cuda_runtime.h>
#include <cuda_bf16.h>

#define BATCH 1024
#define SEQ   256
#define HALF  128

typedef unsigned long long u64;

__device__ __forceinline__ u64 pack2(float lo, float hi) {
    u64 r; asm("mov.b64 %0, {%1,%2};" : "=l"(r) : "f"(lo), "f"(hi)); return r;
}
__device__ __forceinline__ void unpack2(u64 v, float& lo, float& hi) {
    asm("mov.b64 {%0,%1}, %2;" : "=f"(lo), "=f"(hi) : "l"(v));
}
__device__ __forceinline__ u64 ffma2(u64 a, u64 b, u64 c) {
    u64 d; asm("fma.rn.f32x2 %0, %1, %2, %3;" : "=l"(d) : "l"(a), "l"(b), "l"(c)); return d;
}
__device__ __forceinline__ u64 fmul2(u64 a, u64 b) {
    u64 d; asm("mul.rn.f32x2 %0, %1, %2;" : "=l"(d) : "l"(a), "l"(b)); return d;
}
__device__ __forceinline__ float ex2f(float x) {
    float r; asm("ex2.approx.f32 %0, %1;" : "=f"(r) : "f"(x)); return r;
}

// TWO CTAs per batch element (grid = 2048): each CTA redundantly builds the
// full 256-row K/V tile (cheap prologue), then handles 128 query rows with
// ONE row per thread. Doubles resident warps vs R8 (the kernel was
// grid-occupancy-limited, not FMA-limited): same total FMA warp-instrs,
// twice the latency hiding for the dot->EX2->accum chain.
// K pre-scaled by 0.5*log2e; pair-packed f32x2 K/V in SMEM as in R8.
__global__ __launch_bounds__(HALF, 10) void hybrid_attn_kernel(
    const float* __restrict__ x,
    const float* __restrict__ Wq, const float* __restrict__ Wk, const float* __restrict__ Wv,
    const float* __restrict__ W1, const float* __restrict__ b1,
    const float* __restrict__ W2, const float* __restrict__ b2,
    const float* __restrict__ W3, const float* __restrict__ b3,
    float* __restrict__ out)
{
    __shared__ ulonglong2 sk[SEQ];   // .x = (k0*cs, k1*cs), .y = (k2*cs, k3*cs)
    __shared__ ulonglong2 sv[SEQ];   // .x = (v0, v1),       .y = (v2, v3)
    __shared__ float sWq[16], sWk[16], sWv[16];
    __shared__ float sW1[32], sb1[8], sW2[32], sb2[4], sW3[4], sb3;

    const int tid = threadIdx.x;
    const int b   = blockIdx.x >> 1;        // batch element
    const int h   = blockIdx.x & 1;         // which half of the query rows
    const int qrow = h * HALF + tid;        // this thread's query row

    if (tid < 16) { sWq[tid] = Wq[tid]; sWk[tid] = Wk[tid]; sWv[tid] = Wv[tid]; }
    if (tid < 32) { sW1[tid] = W1[tid]; sW2[tid] = W2[tid]; }
    if (tid < 8)  { sb1[tid] = b1[tid]; }
    if (tid < 4)  { sb2[tid] = b2[tid]; sW3[tid] = W3[tid]; }
    if (tid == 0) { sb3 = b3[0]; }

    // K/V source rows this thread projects (full tile needed by every CTA),
    // plus the x row for this thread's own query.
    const float4 xa = reinterpret_cast<const float4*>(x)[b * SEQ + tid];
    const float4 xb = reinterpret_cast<const float4*>(x)[b * SEQ + tid + HALF];
    const float4 xq = (h == 0) ? xa : xb;

    __syncthreads();   // weights staged before any read

    #define PROJ(W, xv, o0, o1, o2, o3)                                        \
        o0 = xv.x*W[0] + xv.y*W[4] + xv.z*W[8]  + xv.w*W[12];                  \
        o1 = xv.x*W[1] + xv.y*W[5] + xv.z*W[9]  + xv.w*W[13];                  \
        o2 = xv.x*W[2] + xv.y*W[6] + xv.z*W[10] + xv.w*W[14];                  \
        o3 = xv.x*W[3] + xv.y*W[7] + xv.z*W[11] + xv.w*W[15];

    const float cs = 0.72134752044448170368f;   // 0.5 * log2(e), folded into K

    float t0,t1,t2,t3;
    PROJ(sWk, xa, t0,t1,t2,t3)
    sk[tid]        = make_ulonglong2(pack2(t0*cs, t1*cs), pack2(t2*cs, t3*cs));
    PROJ(sWk, xb, t0,t1,t2,t3)
    sk[tid + HALF] = make_ulonglong2(pack2(t0*cs, t1*cs), pack2(t2*cs, t3*cs));
    PROJ(sWv, xa, t0,t1,t2,t3)
    sv[tid]        = make_ulonglong2(pack2(t0, t1), pack2(t2, t3));
    PROJ(sWv, xb, t0,t1,t2,t3)
    sv[tid + HALF] = make_ulonglong2(pack2(t0, t1), pack2(t2, t3));

    float q0,q1,q2,q3;
    PROJ(sWq, xq, q0,q1,q2,q3)
    #undef PROJ

    const u64 q01 = pack2(q0, q1), q23 = pack2(q2, q3);

    __syncthreads();

    u64 acc01 = 0, acc23 = 0;      // 0ull == (0.0f, 0.0f)
    float l = 0.0f;

    #pragma unroll 8
    for (int t = 0; t < SEQ; ++t) {
        const ulonglong2 kk = sk[t];   // one LDS.128, pair-aligned
        const ulonglong2 vv = sv[t];   // one LDS.128, pair-aligned

        u64 p = ffma2(q01, kk.x, fmul2(q23, kk.y));
        float p0, p1; unpack2(p, p0, p1);
        const float e = ex2f(p0 + p1);
        const u64 ee = pack2(e, e);
        acc01 = ffma2(ee, vv.x, acc01);
        acc23 = ffma2(ee, vv.y, acc23);
        l += e;
    }

    float a0, a1, a2, a3;
    unpack2(acc01, a0, a1);
    unpack2(acc23, a2, a3);
    const float inv = 1.0f / l;
    a0 *= inv; a1 *= inv; a2 *= inv; a3 *= inv;

    // MLP head: 4 -> 8 (tanh) -> 4 (tanh) -> 1
    float h1[8];
    #pragma unroll
    for (int i = 0; i < 8; ++i) {
        float u = a0*sW1[0*8+i] + a1*sW1[1*8+i] + a2*sW1[2*8+i] + a3*sW1[3*8+i] + sb1[i];
        h1[i] = tanhf(u);
    }
    float h2[4];
    #pragma unroll
    for (int i = 0; i < 4; ++i) {
        float u = sb2[i];
        #pragma unroll
        for (int j = 0; j < 8; ++j) u += h1[j] * sW2[j*4+i];
        h2[i] = tanhf(u);
    }
    float o = h2[0]*sW3[0] + h2[1]*sW3[1] + h2[2]*sW3[2] + h2[3]*sW3[3] + sb3;

    out[b * SEQ + qrow] = o;
}

extern "C" void kernel_launch(void* const* d_in, const int* in_sizes, int n_in,
                              void* d_out, int out_size) {
    const float* x  = (const float*)d_in[0];
    const float* Wq = (const float*)d_in[1];
    const float* Wk = (const float*)d_in[2];
    const float* Wv = (const float*)d_in[3];
    const float* W1 = (const float*)d_in[4];
    const float* b1 = (const float*)d_in[5];
    const float* W2 = (const float*)d_in[6];
    const float* b2 = (const float*)d_in[7];
    const float* W3 = (const float*)d_in[8];
    const float* b3 = (const float*)d_in[9];
    float* out = (float*)d_out;

    hybrid_attn_kernel<<<BATCH * 2, HALF>>>(x, Wq, Wk, Wv, W1, b1, W2, b2, W3, b3, out);
}

// round 11
// speedup vs baseline: 1.0294x; 1.0294x over previous
#include <cuda_runtime.h>
#include <cuda_bf16.h>

#define BATCH 1024
#define SEQ   256
#define NT    64      // threads per CTA
#define RPT   4       // query rows per thread

typedef unsigned long long u64;

__device__ __forceinline__ u64 pack2(float lo, float hi) {
    u64 r; asm("mov.b64 %0, {%1,%2};" : "=l"(r) : "f"(lo), "f"(hi)); return r;
}
__device__ __forceinline__ void unpack2(u64 v, float& lo, float& hi) {
    asm("mov.b64 {%0,%1}, %2;" : "=f"(lo), "=f"(hi) : "l"(v));
}
__device__ __forceinline__ u64 ffma2(u64 a, u64 b, u64 c) {
    u64 d; asm("fma.rn.f32x2 %0, %1, %2, %3;" : "=l"(d) : "l"(a), "l"(b), "l"(c)); return d;
}
__device__ __forceinline__ u64 fmul2(u64 a, u64 b) {
    u64 d; asm("mul.rn.f32x2 %0, %1, %2;" : "=l"(d) : "l"(a), "l"(b)); return d;
}
__device__ __forceinline__ float ex2f(float x) {
    float r; asm("ex2.approx.f32 %0, %1;" : "=f"(r) : "f"(x)); return r;
}

// One CTA per batch element, 64 threads, FOUR query rows per thread.
// Rationale (R10 post-mortem): kernel is issue/latency-bound around the
// LDS->dot->EX2->accum chain; occupancy increases didn't help (R8/R10) and
// 1-row/thread doubled LDS traffic to L1=70%. 4 rows/thread amortizes the
// two LDS.128 per t over 4 independent chains: fma share of issue slots
// rises ~55%->~71%, L1 drops to ~18%, ILP covers the chain latency inside
// each warp. K pre-scaled by 0.5*log2(e); f32x2 packed math throughout.
__global__ __launch_bounds__(NT) void hybrid_attn_kernel(
    const float* __restrict__ x,
    const float* __restrict__ Wq, const float* __restrict__ Wk, const float* __restrict__ Wv,
    const float* __restrict__ W1, const float* __restrict__ b1,
    const float* __restrict__ W2, const float* __restrict__ b2,
    const float* __restrict__ W3, const float* __restrict__ b3,
    float* __restrict__ out)
{
    __shared__ ulonglong2 sk[SEQ];   // .x = (k0*cs, k1*cs), .y = (k2*cs, k3*cs)
    __shared__ ulonglong2 sv[SEQ];   // .x = (v0, v1),       .y = (v2, v3)
    __shared__ float sWq[16], sWk[16], sWv[16];
    __shared__ float sW1[32], sb1[8], sW2[32], sb2[4], sW3[4], sb3;

    const int tid = threadIdx.x;
    const int b   = blockIdx.x;

    if (tid < 16) { sWq[tid] = Wq[tid]; sWk[tid] = Wk[tid]; sWv[tid] = Wv[tid]; }
    if (tid < 32) { sW1[tid] = W1[tid]; sW2[tid] = W2[tid]; }
    if (tid < 8)  { sb1[tid] = b1[tid]; }
    if (tid < 4)  { sb2[tid] = b2[tid]; sW3[tid] = W3[tid]; }
    if (tid == 0) { sb3 = b3[0]; }

    // Four x rows per thread (overlaps the barrier).
    float4 xr[RPT];
    #pragma unroll
    for (int i = 0; i < RPT; ++i)
        xr[i] = reinterpret_cast<const float4*>(x)[b * SEQ + tid + i * NT];

    __syncthreads();   // weights staged before any read

    #define PROJ(W, xv, o0, o1, o2, o3)                                        \
        o0 = xv.x*W[0] + xv.y*W[4] + xv.z*W[8]  + xv.w*W[12];                  \
        o1 = xv.x*W[1] + xv.y*W[5] + xv.z*W[9]  + xv.w*W[13];                  \
        o2 = xv.x*W[2] + xv.y*W[6] + xv.z*W[10] + xv.w*W[14];                  \
        o3 = xv.x*W[3] + xv.y*W[7] + xv.z*W[11] + xv.w*W[15];

    const float cs = 0.72134752044448170368f;   // 0.5 * log2(e), folded into K

    u64 q01[RPT], q23[RPT];
    #pragma unroll
    for (int i = 0; i < RPT; ++i) {
        float t0,t1,t2,t3;
        PROJ(sWk, xr[i], t0,t1,t2,t3)
        sk[tid + i*NT] = make_ulonglong2(pack2(t0*cs, t1*cs), pack2(t2*cs, t3*cs));
        PROJ(sWv, xr[i], t0,t1,t2,t3)
        sv[tid + i*NT] = make_ulonglong2(pack2(t0, t1), pack2(t2, t3));
        PROJ(sWq, xr[i], t0,t1,t2,t3)
        q01[i] = pack2(t0, t1);
        q23[i] = pack2(t2, t3);
    }
    #undef PROJ

    __syncthreads();

    u64 acc01[RPT], acc23[RPT];
    float l[RPT];
    #pragma unroll
    for (int i = 0; i < RPT; ++i) { acc01[i] = 0; acc23[i] = 0; l[i] = 0.0f; }

    #pragma unroll 4
    for (int t = 0; t < SEQ; ++t) {
        const ulonglong2 kk = sk[t];   // one LDS.128 shared by 4 rows
        const ulonglong2 vv = sv[t];   // one LDS.128 shared by 4 rows

        #pragma unroll
        for (int i = 0; i < RPT; ++i) {
            u64 p = ffma2(q01[i], kk.x, fmul2(q23[i], kk.y));
            float p0, p1; unpack2(p, p0, p1);
            const float e = ex2f(p0 + p1);
            const u64 ee = pack2(e, e);
            acc01[i] = ffma2(ee, vv.x, acc01[i]);
            acc23[i] = ffma2(ee, vv.y, acc23[i]);
            l[i] += e;
        }
    }

    // MLP head per row: 4 -> 8 (tanh) -> 4 (tanh) -> 1
    #pragma unroll
    for (int i = 0; i < RPT; ++i) {
        float a0, a1, a2, a3;
        unpack2(acc01[i], a0, a1);
        unpack2(acc23[i], a2, a3);
        const float inv = 1.0f / l[i];
        a0 *= inv; a1 *= inv; a2 *= inv; a3 *= inv;

        float h1[8];
        #pragma unroll
        for (int j = 0; j < 8; ++j) {
            float u = a0*sW1[0*8+j] + a1*sW1[1*8+j] + a2*sW1[2*8+j] + a3*sW1[3*8+j] + sb1[j];
            h1[j] = tanhf(u);
        }
        float h2[4];
        #pragma unroll
        for (int j = 0; j < 4; ++j) {
            float u = sb2[j];
            #pragma unroll
            for (int m = 0; m < 8; ++m) u += h1[m] * sW2[m*4+j];
            h2[j] = tanhf(u);
        }
        float o = h2[0]*sW3[0] + h2[1]*sW3[1] + h2[2]*sW3[2] + h2[3]*sW3[3] + sb3;
        out[b * SEQ + tid + i * NT] = o;
    }
}

extern "C" void kernel_launch(void* const* d_in, const int* in_sizes, int n_in,
                              void* d_out, int out_size) {
    const float* x  = (const float*)d_in[0];
    const float* Wq = (const float*)d_in[1];
    const float* Wk = (const float*)d_in[2];
    const float* Wv = (const float*)d_in[3];
    const float* W1 = (const float*)d_in[4];
    const float* b1 = (const float*)d_in[5];
    const float* W2 = (const float*)d_in[6];
    const float* b2 = (const float*)d_in[7];
    const float* W3 = (const float*)d_in[8];
    const float* b3 = (const float*)d_in[9];
    float* out = (float*)d_out;

    hybrid_attn_kernel<<<BATCH, NT>>>(x, Wq, Wk, Wv, W1, b1, W2, b2, W3, b3, out);
}

// round 14
// speedup vs baseline: 1.0981x; 1.0667x over previous
#include <cuda_runtime.h>
#include <cuda_bf16.h>

#define BATCH 1024
#define SEQ   256
#define HALF  128

typedef unsigned long long u64;

__device__ __forceinline__ u64 pack2(float lo, float hi) {
    u64 r; asm("mov.b64 %0, {%1,%2};" : "=l"(r) : "f"(lo), "f"(hi)); return r;
}
__device__ __forceinline__ void unpack2(u64 v, float& lo, float& hi) {
    asm("mov.b64 {%0,%1}, %2;" : "=f"(lo), "=f"(hi) : "l"(v));
}
__device__ __forceinline__ u64 ffma2(u64 a, u64 b, u64 c) {
    u64 d; asm("fma.rn.f32x2 %0, %1, %2, %3;" : "=l"(d) : "l"(a), "l"(b), "l"(c)); return d;
}
__device__ __forceinline__ u64 fmul2(u64 a, u64 b) {
    u64 d; asm("mul.rn.f32x2 %0, %1, %2;" : "=l"(d) : "l"(a), "l"(b)); return d;
}
__device__ __forceinline__ u64 fadd2(u64 a, u64 b) {
    u64 d; asm("add.rn.f32x2 %0, %1, %2;" : "=l"(d) : "l"(a), "l"(b)); return d;
}
__device__ __forceinline__ float ex2f(float x) {
    float r; asm("ex2.approx.f32 %0, %1;" : "=f"(r) : "f"(x)); return r;
}
__device__ __forceinline__ float rcpf(float x) {
    float r; asm("rcp.approx.f32 %0, %1;" : "=f"(r) : "f"(x)); return r;
}

// Accurate-enough fast tanh: tanh(x) = 1 - 2/(exp(2x)+1).
// ex2.approx + rcp.approx give ~1e-7 abs error (vs 5e-4 for tanh.approx).
// 3 FMA-pipe ops + 2 MUFU, vs ~20 FMA-pipe for libm tanhf.
__device__ __forceinline__ float fast_tanh(float x) {
    const float c = 2.88539008177792681472f;   // 2 * log2(e)
    float e = ex2f(x * c);
    float r = rcpf(e + 1.0f);
    return fmaf(-2.0f, r, 1.0f);
}

// R8 shape (best measured): one CTA per batch, 128 threads, 2 rows/thread,
// pair-packed f32x2 K/V in SMEM, K pre-scaled by 0.5*log2e.
// R12 deltas: (1) l-accumulation packed as (eA,eB) add2 -> inner-loop FMA-pipe
// ops 12 -> 11 per t; (2) epilogue tanhf (480 FMA ops/thread, ~15% of all FMA
// work) replaced by exp-based fast_tanh (72 FMA ops, MUFU has headroom).
__global__ __launch_bounds__(HALF, 8) void hybrid_attn_kernel(
    const float* __restrict__ x,
    const float* __restrict__ Wq, const float* __restrict__ Wk, const float* __restrict__ Wv,
    const float* __restrict__ W1, const float* __restrict__ b1,
    const float* __restrict__ W2, const float* __restrict__ b2,
    const float* __restrict__ W3, const float* __restrict__ b3,
    float* __restrict__ out)
{
    __shared__ ulonglong2 sk[SEQ];   // .x = (k0*cs, k1*cs), .y = (k2*cs, k3*cs)
    __shared__ ulonglong2 sv[SEQ];   // .x = (v0, v1),       .y = (v2, v3)
    __shared__ float sWq[16], sWk[16], sWv[16];
    __shared__ float sW1[32], sb1[8], sW2[32], sb2[4], sW3[4], sb3;

    const int tid = threadIdx.x;
    const int b   = blockIdx.x;

    if (tid < 16) { sWq[tid] = Wq[tid]; sWk[tid] = Wk[tid]; sWv[tid] = Wv[tid]; }
    if (tid < 32) { sW1[tid] = W1[tid]; sW2[tid] = W2[tid]; }
    if (tid < 8)  { sb1[tid] = b1[tid]; }
    if (tid < 4)  { sb2[tid] = b2[tid]; sW3[tid] = W3[tid]; }
    if (tid == 0) { sb3 = b3[0]; }

    const float4 xa = reinterpret_cast<const float4*>(x)[b * SEQ + tid];
    const float4 xb = reinterpret_cast<const float4*>(x)[b * SEQ + tid + HALF];

    __syncthreads();   // weights staged before any read

    #define PROJ(W, xv, o0, o1, o2, o3)                                        \
        o0 = xv.x*W[0] + xv.y*W[4] + xv.z*W[8]  + xv.w*W[12];                  \
        o1 = xv.x*W[1] + xv.y*W[5] + xv.z*W[9]  + xv.w*W[13];                  \
        o2 = xv.x*W[2] + xv.y*W[6] + xv.z*W[10] + xv.w*W[14];                  \
        o3 = xv.x*W[3] + xv.y*W[7] + xv.z*W[11] + xv.w*W[15];

    const float cs = 0.72134752044448170368f;   // 0.5 * log2(e), folded into K

    float qa0,qa1,qa2,qa3, qb0,qb1,qb2,qb3;
    float t0,t1,t2,t3;

    PROJ(sWq, xa, qa0,qa1,qa2,qa3)
    PROJ(sWq, xb, qb0,qb1,qb2,qb3)

    PROJ(sWk, xa, t0,t1,t2,t3)
    sk[tid]        = make_ulonglong2(pack2(t0*cs, t1*cs), pack2(t2*cs, t3*cs));
    PROJ(sWk, xb, t0,t1,t2,t3)
    sk[tid + HALF] = make_ulonglong2(pack2(t0*cs, t1*cs), pack2(t2*cs, t3*cs));

    PROJ(sWv, xa, t0,t1,t2,t3)
    sv[tid]        = make_ulonglong2(pack2(t0, t1), pack2(t2, t3));
    PROJ(sWv, xb, t0,t1,t2,t3)
    sv[tid + HALF] = make_ulonglong2(pack2(t0, t1), pack2(t2, t3));
    #undef PROJ

    const u64 qa01 = pack2(qa0, qa1), qa23 = pack2(qa2, qa3);
    const u64 qb01 = pack2(qb0, qb1), qb23 = pack2(qb2, qb3);

    __syncthreads();

    u64 accA01 = 0, accA23 = 0, accB01 = 0, accB23 = 0;  // 0ull == (0.0f, 0.0f)
    u64 lAB = 0;                                         // (sum eA, sum eB)

    #pragma unroll 4
    for (int t = 0; t < SEQ; ++t) {
        const ulonglong2 kk = sk[t];   // one LDS.128, pair-aligned
        const ulonglong2 vv = sv[t];   // one LDS.128, pair-aligned

        // row A
        u64 pA = ffma2(qa01, kk.x, fmul2(qa23, kk.y));
        float pA0, pA1; unpack2(pA, pA0, pA1);
        float eA = ex2f(pA0 + pA1);
        // row B
        u64 pB = ffma2(qb01, kk.x, fmul2(qb23, kk.y));
        float pB0, pB1; unpack2(pB, pB0, pB1);
        float eB = ex2f(pB0 + pB1);

        u64 eeA = pack2(eA, eA);
        accA01 = ffma2(eeA, vv.x, accA01);
        accA23 = ffma2(eeA, vv.y, accA23);

        u64 eeB = pack2(eB, eB);
        accB01 = ffma2(eeB, vv.x, accB01);
        accB23 = ffma2(eeB, vv.y, accB23);

        lAB = fadd2(lAB, pack2(eA, eB));   // packed denominators (1 fma-pipe op)
    }

    float lA, lB;
    unpack2(lAB, lA, lB);

    // MLP head per row: 4 -> 8 (tanh) -> 4 (tanh) -> 1
    #pragma unroll
    for (int r = 0; r < 2; ++r) {
        float a0, a1, a2, a3, l;
        if (r == 0) { unpack2(accA01, a0, a1); unpack2(accA23, a2, a3); l = lA; }
        else        { unpack2(accB01, a0, a1); unpack2(accB23, a2, a3); l = lB; }
        const float inv = 1.0f / l;
        a0 *= inv; a1 *= inv; a2 *= inv; a3 *= inv;

        float h1[8];
        #pragma unroll
        for (int i = 0; i < 8; ++i) {
            float u = a0*sW1[0*8+i] + a1*sW1[1*8+i] + a2*sW1[2*8+i] + a3*sW1[3*8+i] + sb1[i];
            h1[i] = fast_tanh(u);
        }
        float h2[4];
        #pragma unroll
        for (int i = 0; i < 4; ++i) {
            float u = sb2[i];
            #pragma unroll
            for (int j = 0; j < 8; ++j) u += h1[j] * sW2[j*4+i];
            h2[i] = fast_tanh(u);
        }
        float o = h2[0]*sW3[0] + h2[1]*sW3[1] + h2[2]*sW3[2] + h2[3]*sW3[3] + sb3;
        out[b * SEQ + tid + r * HALF] = o;
    }
}

extern "C" void kernel_launch(void* const* d_in, const int* in_sizes, int n_in,
                              void* d_out, int out_size) {
    const float* x  = (const float*)d_in[0];
    const float* Wq = (const float*)d_in[1];
    const float* Wk = (const float*)d_in[2];
    const float* Wv = (const float*)d_in[3];
    const float* W1 = (const float*)d_in[4];
    const float* b1 = (const float*)d_in[5];
    const float* W2 = (const float*)d_in[6];
    const float* b2 = (const float*)d_in[7];
    const float* W3 = (const float*)d_in[8];
    const float* b3 = (const float*)d_in[9];
    float* out = (float*)d_out;

    hybrid_attn_kernel<<<BATCH, HALF>>>(x, Wq, Wk, Wv, W1, b1, W2, b2, W3, b3, out);
}